// round 12
// baseline (speedup 1.0000x reference)
#include <cuda_runtime.h>
#include <cuda_bf16.h>
#include <cuda_fp16.h>

#define N_NODES 10000
#define N_EDGES 320000
#define IN_DIM  128
#define HID     256
#define HID4    1024
#define BKT     192      // bucket capacity: deg ~ Poisson(32), 192 = +28 sigma

// ---------------- scratch (static device globals; no allocation) ----------------
__device__ float  g_gates[HID * HID4];   // IW @ (W_ih+W_hh)^T + b_ih + b_hh   [H, 4H]
__device__ float  g_W[HID * HID];        // evolved GCN weight                 [H, H]
__device__ float  g_Wc[IN_DIM * HID];    // Wp @ W                             [IN, H]
__device__ float  g_bc[HID];             // bp @ W                             [H]
__device__ float  g_y[N_NODES * IN_DIM]; // aggregated scaled features        [N, IN]
__device__ float  g_u[N_NODES];          // dinv[i] + sum_in dinv[s]
__device__ int    g_cur[N_NODES];        // fill cursor == in-degree after fill
__device__ int    g_bkt[N_NODES * BKT];  // per-dst src buckets
__device__ __half g_xh[N_NODES * IN_DIM];// fp16 copy of x for neighbor gathers

// ---------------- streams/events (created at static init) ----------------
static cudaStream_t g_s2 = nullptr, g_s3 = nullptr;
static cudaEvent_t g_evFork = nullptr, g_evJoin = nullptr, g_evW = nullptr;
static cudaEvent_t g_evBC = nullptr, g_evX = nullptr;
namespace {
struct StreamInit {
    StreamInit() {
        cudaStreamCreateWithFlags(&g_s2, cudaStreamNonBlocking);
        cudaStreamCreateWithFlags(&g_s3, cudaStreamNonBlocking);
        cudaEventCreateWithFlags(&g_evFork, cudaEventDisableTiming);
        cudaEventCreateWithFlags(&g_evJoin, cudaEventDisableTiming);
        cudaEventCreateWithFlags(&g_evW, cudaEventDisableTiming);
        cudaEventCreateWithFlags(&g_evBC, cudaEventDisableTiming);
        cudaEventCreateWithFlags(&g_evX, cudaEventDisableTiming);
    }
};
static StreamInit g_si;
}

__device__ __forceinline__ float dinv_of(int cur) {
    return rsqrtf((float)cur + 1.0f);
}

// ---------------- x -> fp16 conversion (8 elems/thread) ----------------
__global__ void k_xhalf(const float4* __restrict__ x4) {
    int t = blockIdx.x * blockDim.x + threadIdx.x;
    if (t >= N_NODES * IN_DIM / 8) return;
    float4 a = x4[t * 2];
    float4 b = x4[t * 2 + 1];
    __half2 h0 = __floats2half2_rn(a.x, a.y);
    __half2 h1 = __floats2half2_rn(a.z, a.w);
    __half2 h2 = __floats2half2_rn(b.x, b.y);
    __half2 h3 = __floats2half2_rn(b.z, b.w);
    uint4 packed;
    packed.x = *reinterpret_cast<unsigned*>(&h0);
    packed.y = *reinterpret_cast<unsigned*>(&h1);
    packed.z = *reinterpret_cast<unsigned*>(&h2);
    packed.w = *reinterpret_cast<unsigned*>(&h3);
    reinterpret_cast<uint4*>(g_xh)[t] = packed;
}

// ---------------- graph prologue ----------------
// 4 edges per thread, vectorized loads
__global__ void k_fill(const int* __restrict__ ei) {
    int t = blockIdx.x * blockDim.x + threadIdx.x;
    if (t >= N_EDGES / 4) return;
    int4 s4 = *reinterpret_cast<const int4*>(ei + t * 4);
    int4 d4 = *reinterpret_cast<const int4*>(ei + N_EDGES + t * 4);
    int s[4] = {s4.x, s4.y, s4.z, s4.w};
    int d[4] = {d4.x, d4.y, d4.z, d4.w};
    #pragma unroll
    for (int q = 0; q < 4; q++) {
        int pos = atomicAdd(&g_cur[d[q]], 1);
        if (pos < BKT) g_bkt[d[q] * BKT + pos] = s[q];
    }
}

// one warp per dst node:
// y[i,:] = x[i,:]*dinv[i] (fp32 self) + sum_{s in N(i)} xh[s,:]*dinv[s] (fp16 neighbors)
// u[i]   = dinv[i] + sum dinv[s]
__global__ void k_gather(const float4* __restrict__ x4) {
    int n = (blockIdx.x * blockDim.x + threadIdx.x) >> 5;
    int lane = threadIdx.x & 31;
    if (n >= N_NODES) return;

    const int deg = min(g_cur[n], BKT);
    const int* bkt = g_bkt + (size_t)n * BKT;
    const uint2* xh2 = reinterpret_cast<const uint2*>(g_xh);   // 4 halves per uint2

    float di = dinv_of(deg);
    float4 xv = __ldg(x4 + (size_t)n * 32 + lane);
    float4 acc = make_float4(xv.x * di, xv.y * di, xv.z * di, xv.w * di);
    float tsum = di;

    for (int c = 0; c < deg; c += 32) {
        int m = min(32, deg - c);
        int idx = 0;
        float dv = 0.0f;
        if (lane < m) {
            idx = __ldg(bkt + c + lane);
            dv = dinv_of(__ldg(g_cur + idx));
        }
        int j = 0;
        for (; j + 4 <= m; j += 4) {
            int s0 = __shfl_sync(0xffffffffu, idx, j);
            int s1 = __shfl_sync(0xffffffffu, idx, j + 1);
            int s2 = __shfl_sync(0xffffffffu, idx, j + 2);
            int s3 = __shfl_sync(0xffffffffu, idx, j + 3);
            float w0 = __shfl_sync(0xffffffffu, dv, j);
            float w1 = __shfl_sync(0xffffffffu, dv, j + 1);
            float w2 = __shfl_sync(0xffffffffu, dv, j + 2);
            float w3 = __shfl_sync(0xffffffffu, dv, j + 3);
            uint2 p0 = __ldg(xh2 + (size_t)s0 * 32 + lane);
            uint2 p1 = __ldg(xh2 + (size_t)s1 * 32 + lane);
            uint2 p2 = __ldg(xh2 + (size_t)s2 * 32 + lane);
            uint2 p3 = __ldg(xh2 + (size_t)s3 * 32 + lane);
            float2 a0 = __half22float2(*reinterpret_cast<__half2*>(&p0.x));
            float2 b0 = __half22float2(*reinterpret_cast<__half2*>(&p0.y));
            float2 a1 = __half22float2(*reinterpret_cast<__half2*>(&p1.x));
            float2 b1 = __half22float2(*reinterpret_cast<__half2*>(&p1.y));
            float2 a2 = __half22float2(*reinterpret_cast<__half2*>(&p2.x));
            float2 b2 = __half22float2(*reinterpret_cast<__half2*>(&p2.y));
            float2 a3 = __half22float2(*reinterpret_cast<__half2*>(&p3.x));
            float2 b3 = __half22float2(*reinterpret_cast<__half2*>(&p3.y));
            acc.x = fmaf(a0.x, w0, acc.x); acc.y = fmaf(a0.y, w0, acc.y);
            acc.z = fmaf(b0.x, w0, acc.z); acc.w = fmaf(b0.y, w0, acc.w);
            acc.x = fmaf(a1.x, w1, acc.x); acc.y = fmaf(a1.y, w1, acc.y);
            acc.z = fmaf(b1.x, w1, acc.z); acc.w = fmaf(b1.y, w1, acc.w);
            acc.x = fmaf(a2.x, w2, acc.x); acc.y = fmaf(a2.y, w2, acc.y);
            acc.z = fmaf(b2.x, w2, acc.z); acc.w = fmaf(b2.y, w2, acc.w);
            acc.x = fmaf(a3.x, w3, acc.x); acc.y = fmaf(a3.y, w3, acc.y);
            acc.z = fmaf(b3.x, w3, acc.z); acc.w = fmaf(b3.y, w3, acc.w);
            tsum += w0 + w1 + w2 + w3;
        }
        for (; j < m; j++) {
            int s = __shfl_sync(0xffffffffu, idx, j);
            float ws = __shfl_sync(0xffffffffu, dv, j);
            uint2 p = __ldg(xh2 + (size_t)s * 32 + lane);
            float2 a = __half22float2(*reinterpret_cast<__half2*>(&p.x));
            float2 b = __half22float2(*reinterpret_cast<__half2*>(&p.y));
            acc.x = fmaf(a.x, ws, acc.x); acc.y = fmaf(a.y, ws, acc.y);
            acc.z = fmaf(b.x, ws, acc.z); acc.w = fmaf(b.y, ws, acc.w);
            tsum += ws;
        }
    }

    reinterpret_cast<float4*>(g_y)[(size_t)n * 32 + lane] = acc;
    if (lane == 0) g_u[n] = tsum;
}

// ---------------- weight-evolution elementwise ----------------
__device__ __forceinline__ float tanh_fast(float x) {
    float r;
    asm("tanh.approx.f32 %0, %1;" : "=f"(r) : "f"(x));
    return r;
}
__device__ __forceinline__ float sig_fast(float x) {
    return 0.5f * tanh_fast(0.5f * x) + 0.5f;
}

__global__ void k_evolve(const float* __restrict__ iw) {
    int t = blockIdx.x * blockDim.x + threadIdx.x;
    if (t >= HID * HID) return;
    int r = t >> 8;
    int j = t & (HID - 1);
    const float* gr = g_gates + r * HID4;
    float ig = sig_fast(gr[j]);
    float fg = sig_fast(gr[HID + j]);
    float gg = tanh_fast(gr[2 * HID + j]);
    float og = sig_fast(gr[3 * HID + j]);
    float c = fg * iw[t] + ig * gg;
    g_W[t] = og * tanh_fast(c);
}

// bc[j] = sum_k bp[k] * W[k, j]   (16 blocks x 256 threads, 16-way k split)
__global__ void k_bc(const float* __restrict__ bp) {
    __shared__ float red[16][17];
    int c  = threadIdx.x & 15;
    int kk = threadIdx.x >> 4;
    int col = blockIdx.x * 16 + c;
    float acc = 0.0f;
    #pragma unroll
    for (int t = 0; t < 16; t++) {
        int k = kk + t * 16;
        acc += bp[k] * g_W[k * HID + col];
    }
    red[kk][c] = acc;
    __syncthreads();
    if (kk == 0) {
        float s = 0.0f;
        #pragma unroll
        for (int t = 0; t < 16; t++) s += red[t][c];
        g_bc[col] = s;
    }
}

// ---------------- small tiled fp32 GEMM, software-pipelined ----------------
template<bool TB, bool FUSEB>
__global__ void sgemm(const float* __restrict__ A, const float* __restrict__ B,
                      const float* __restrict__ B2,
                      const float* __restrict__ bias, const float* __restrict__ bias2,
                      float* __restrict__ C, int M, int N, int K) {
    __shared__ float As[16][68];
    __shared__ float Bs[16][68];
    const int tx = threadIdx.x, ty = threadIdx.y;
    const int tid = ty * 16 + tx;
    const int row0 = blockIdx.y * 64;
    const int col0 = blockIdx.x * 64;

    const int ar = tid >> 2;
    const int akq = (tid & 3) * 4;
    const int arow = row0 + ar;
    const bool aok = arow < M;
    const float* Ap = A + (size_t)(aok ? arow : 0) * K + akq;

    const int bk_nt = tid >> 4;
    const int bc_nt = (tid & 15) * 4;
    const float* Bp_nt  = B + (size_t)bk_nt * N + col0 + bc_nt;
    const float* B2p_nt = FUSEB ? (B2 + (size_t)bk_nt * N + col0 + bc_nt) : nullptr;

    const int bc_t = tid >> 2;
    const int bkq_t = (tid & 3) * 4;
    const float* Bp_t  = B + (size_t)(col0 + bc_t) * K + bkq_t;
    const float* B2p_t = FUSEB ? (B2 + (size_t)(col0 + bc_t) * K + bkq_t) : nullptr;

    float acc[4][4] = {};

    float4 aR = aok ? *reinterpret_cast<const float4*>(Ap) : make_float4(0.f, 0.f, 0.f, 0.f);
    float4 bR, b2R;
    if (!TB) {
        bR = *reinterpret_cast<const float4*>(Bp_nt);
        if (FUSEB) b2R = *reinterpret_cast<const float4*>(B2p_nt);
    } else {
        bR = *reinterpret_cast<const float4*>(Bp_t);
        if (FUSEB) b2R = *reinterpret_cast<const float4*>(B2p_t);
    }

    for (int kt = 0; kt < K; kt += 16) {
        As[akq + 0][ar] = aR.x; As[akq + 1][ar] = aR.y;
        As[akq + 2][ar] = aR.z; As[akq + 3][ar] = aR.w;
        {
            float4 v = bR;
            if (FUSEB) { v.x += b2R.x; v.y += b2R.y; v.z += b2R.z; v.w += b2R.w; }
            if (!TB) {
                *reinterpret_cast<float4*>(&Bs[bk_nt][bc_nt]) = v;
            } else {
                Bs[bkq_t + 0][bc_t] = v.x; Bs[bkq_t + 1][bc_t] = v.y;
                Bs[bkq_t + 2][bc_t] = v.z; Bs[bkq_t + 3][bc_t] = v.w;
            }
        }
        __syncthreads();

        if (kt + 16 < K) {
            int knext = kt + 16;
            aR = aok ? *reinterpret_cast<const float4*>(Ap + knext) : make_float4(0.f, 0.f, 0.f, 0.f);
            if (!TB) {
                bR = *reinterpret_cast<const float4*>(Bp_nt + (size_t)knext * N);
                if (FUSEB) b2R = *reinterpret_cast<const float4*>(B2p_nt + (size_t)knext * N);
            } else {
                bR = *reinterpret_cast<const float4*>(Bp_t + knext);
                if (FUSEB) b2R = *reinterpret_cast<const float4*>(B2p_t + knext);
            }
        }

        #pragma unroll
        for (int k = 0; k < 16; k++) {
            float4 a = *reinterpret_cast<const float4*>(&As[k][ty * 4]);
            float4 b = *reinterpret_cast<const float4*>(&Bs[k][tx * 4]);
            float av[4] = {a.x, a.y, a.z, a.w};
            float bv[4] = {b.x, b.y, b.z, b.w};
            #pragma unroll
            for (int i = 0; i < 4; i++)
                #pragma unroll
                for (int j = 0; j < 4; j++)
                    acc[i][j] = fmaf(av[i], bv[j], acc[i][j]);
        }
        __syncthreads();
    }

    #pragma unroll
    for (int i = 0; i < 4; i++) {
        int row = row0 + ty * 4 + i;
        if (row >= M) continue;
        int col = col0 + tx * 4;
        float4 v = make_float4(acc[i][0], acc[i][1], acc[i][2], acc[i][3]);
        if (bias) {
            const float4 bb = *reinterpret_cast<const float4*>(bias + col);
            v.x += bb.x; v.y += bb.y; v.z += bb.z; v.w += bb.w;
        }
        if (bias2) {
            const float4 bb = *reinterpret_cast<const float4*>(bias2 + col);
            v.x += bb.x; v.y += bb.y; v.z += bb.z; v.w += bb.w;
        }
        *reinterpret_cast<float4*>(C + (size_t)row * N + col) = v;
    }
}

// ---------------- main GEMM (f32x2 packed FMA, software-pipelined) ----------------
__global__ void k_main_gemm(const float* __restrict__ bgcn, float* __restrict__ out) {
    __shared__ float As[16][132];
    __shared__ float Bs[16][68];
    const int tid = threadIdx.x;           // 256 threads
    const int tx = tid & 15;
    const int ty = tid >> 4;
    const int row0 = blockIdx.y * 128;
    const int col0 = blockIdx.x * 64;
    const int M = N_NODES, N = HID, K = IN_DIM;

    const int ar0 = tid >> 2, ar1 = (tid + 256) >> 2;
    const int akq = (tid & 3) * 4;
    const int arow0 = row0 + ar0, arow1 = row0 + ar1;
    const bool aok0 = arow0 < M, aok1 = arow1 < M;
    const float* Ap0 = g_y + (size_t)(aok0 ? arow0 : 0) * K + akq;
    const float* Ap1 = g_y + (size_t)(aok1 ? arow1 : 0) * K + akq;
    const int bk = tid >> 4;
    const int bcq = (tid & 15) * 4;
    const float* Bp = g_Wc + (size_t)bk * N + col0 + bcq;

    unsigned long long acc2[4][4] = {};

    float4 aR0 = aok0 ? *reinterpret_cast<const float4*>(Ap0) : make_float4(0.f, 0.f, 0.f, 0.f);
    float4 aR1 = aok1 ? *reinterpret_cast<const float4*>(Ap1) : make_float4(0.f, 0.f, 0.f, 0.f);
    float4 bRv = *reinterpret_cast<const float4*>(Bp);

    for (int kt = 0; kt < K; kt += 16) {
        As[akq + 0][ar0] = aR0.x; As[akq + 1][ar0] = aR0.y;
        As[akq + 2][ar0] = aR0.z; As[akq + 3][ar0] = aR0.w;
        As[akq + 0][ar1] = aR1.x; As[akq + 1][ar1] = aR1.y;
        As[akq + 2][ar1] = aR1.z; As[akq + 3][ar1] = aR1.w;
        *reinterpret_cast<float4*>(&Bs[bk][bcq]) = bRv;
        __syncthreads();

        if (kt + 16 < K) {
            int knext = kt + 16;
            aR0 = aok0 ? *reinterpret_cast<const float4*>(Ap0 + knext) : make_float4(0.f, 0.f, 0.f, 0.f);
            aR1 = aok1 ? *reinterpret_cast<const float4*>(Ap1 + knext) : make_float4(0.f, 0.f, 0.f, 0.f);
            bRv = *reinterpret_cast<const float4*>(Bp + (size_t)knext * N);
        }

        #pragma unroll
        for (int k = 0; k < 16; k++) {
            unsigned long long ap[4];
            #pragma unroll
            for (int i2 = 0; i2 < 4; i2++)
                ap[i2] = *reinterpret_cast<const unsigned long long*>(&As[k][ty * 8 + 2 * i2]);
            float4 b = *reinterpret_cast<const float4*>(&Bs[k][tx * 4]);
            unsigned long long bp0, bp1, bp2, bp3;
            asm("mov.b64 %0, {%1, %1};" : "=l"(bp0) : "f"(b.x));
            asm("mov.b64 %0, {%1, %1};" : "=l"(bp1) : "f"(b.y));
            asm("mov.b64 %0, {%1, %1};" : "=l"(bp2) : "f"(b.z));
            asm("mov.b64 %0, {%1, %1};" : "=l"(bp3) : "f"(b.w));
            #pragma unroll
            for (int i2 = 0; i2 < 4; i2++) {
                asm("fma.rn.f32x2 %0, %1, %2, %0;" : "+l"(acc2[i2][0]) : "l"(ap[i2]), "l"(bp0));
                asm("fma.rn.f32x2 %0, %1, %2, %0;" : "+l"(acc2[i2][1]) : "l"(ap[i2]), "l"(bp1));
                asm("fma.rn.f32x2 %0, %1, %2, %0;" : "+l"(acc2[i2][2]) : "l"(ap[i2]), "l"(bp2));
                asm("fma.rn.f32x2 %0, %1, %2, %0;" : "+l"(acc2[i2][3]) : "l"(ap[i2]), "l"(bp3));
            }
        }
        __syncthreads();
    }

    const int col = col0 + tx * 4;
    const float4 bc4 = *reinterpret_cast<const float4*>(g_bc + col);
    const float4 bg4 = *reinterpret_cast<const float4*>(bgcn + col);
    #pragma unroll
    for (int i2 = 0; i2 < 4; i2++) {
        float lo[4], hi[4];
        #pragma unroll
        for (int j = 0; j < 4; j++)
            asm("mov.b64 {%0, %1}, %2;" : "=f"(lo[j]), "=f"(hi[j]) : "l"(acc2[i2][j]));
        #pragma unroll
        for (int h = 0; h < 2; h++) {
            int row = row0 + ty * 8 + 2 * i2 + h;
            if (row >= M) continue;
            float* a = h ? hi : lo;
            float sc = dinv_of(min(g_cur[row], BKT));
            float uu = g_u[row] * sc;
            float4 v;
            v.x = a[0] * sc + bc4.x * uu + bg4.x;
            v.y = a[1] * sc + bc4.y * uu + bg4.y;
            v.z = a[2] * sc + bc4.z * uu + bg4.z;
            v.w = a[3] * sc + bc4.w * uu + bg4.w;
            *reinterpret_cast<float4*>(out + (size_t)row * N + col) = v;
        }
    }
}

// ---------------- launch ----------------
extern "C" void kernel_launch(void* const* d_in, const int* in_sizes, int n_in,
                              void* d_out, int out_size) {
    const float* x    = (const float*)d_in[0];
    const int*   ei   = (const int*)d_in[1];      // jax int64 is silently int32 (x64 disabled)
    const float* Wp   = (const float*)d_in[2];
    const float* bp   = (const float*)d_in[3];
    const float* W_ih = (const float*)d_in[4];
    const float* W_hh = (const float*)d_in[5];
    const float* b_ih = (const float*)d_in[6];
    const float* b_hh = (const float*)d_in[7];
    const float* IW   = (const float*)d_in[8];
    const float* bgcn = (const float*)d_in[9];
    float* out = (float*)d_out;

    float* d_gates; cudaGetSymbolAddress((void**)&d_gates, g_gates);
    float* d_W;     cudaGetSymbolAddress((void**)&d_W,     g_W);
    float* d_Wc;    cudaGetSymbolAddress((void**)&d_Wc,    g_Wc);
    int*   d_cur;   cudaGetSymbolAddress((void**)&d_cur,   g_cur);

    dim3 thr(16, 16);

    cudaEventRecord(g_evFork, 0);

    // stream3: x -> fp16 (fast, done before gather needs it), then k_bc after evolve
    cudaStreamWaitEvent(g_s3, g_evFork, 0);
    k_xhalf<<<(N_NODES * IN_DIM / 8 + 255) / 256, 256, 0, g_s3>>>((const float4*)x);
    cudaEventRecord(g_evX, g_s3);

    // stream2: weight-evolution chain
    cudaStreamWaitEvent(g_s2, g_evFork, 0);
    sgemm<true, true><<<dim3(HID4 / 64, HID / 64), thr, 0, g_s2>>>(
        IW, W_ih, W_hh, b_ih, b_hh, d_gates, HID, HID4, HID);
    k_evolve<<<(HID * HID + 255) / 256, 256, 0, g_s2>>>(IW);
    cudaEventRecord(g_evW, g_s2);
    sgemm<false, false><<<dim3(HID / 64, IN_DIM / 64), thr, 0, g_s2>>>(
        Wp, d_W, nullptr, nullptr, nullptr, d_Wc, IN_DIM, HID, HID);
    cudaEventRecord(g_evJoin, g_s2);

    // stream3 (continued): k_bc after evolve, parallel with Wc GEMM
    cudaStreamWaitEvent(g_s3, g_evW, 0);
    k_bc<<<16, 256, 0, g_s3>>>(bp);
    cudaEventRecord(g_evBC, g_s3);

    // graph chain on default stream
    cudaMemsetAsync(d_cur, 0, N_NODES * sizeof(int), 0);
    k_fill<<<(N_EDGES / 4 + 255) / 256, 256>>>(ei);
    cudaStreamWaitEvent(0, g_evX, 0);
    k_gather<<<(N_NODES * 32 + 255) / 256, 256>>>((const float4*)x);

    // join, then final GEMM
    cudaStreamWaitEvent(0, g_evJoin, 0);
    cudaStreamWaitEvent(0, g_evBC, 0);
    k_main_gemm<<<dim3(HID / 64, (N_NODES + 127) / 128), 256>>>(bgcn, out);
}

// round 13
// speedup vs baseline: 1.4746x; 1.4746x over previous
#include <cuda_runtime.h>
#include <cuda_bf16.h>

#define N_NODES 10000
#define N_EDGES 320000
#define IN_DIM  128
#define HID     256
#define HID4    1024
#define BKT     192      // bucket capacity: deg ~ Poisson(32), 192 = +28 sigma

// ---------------- scratch (static device globals; no allocation) ----------------
__device__ float g_W[HID * HID];        // evolved GCN weight                 [H, H]
__device__ float g_Wc[IN_DIM * HID];    // Wp @ W                             [IN, H]
__device__ float g_bc[HID];             // bp @ W                             [H]
__device__ float g_y[N_NODES * IN_DIM]; // aggregated scaled features        [N, IN]
__device__ float g_u[N_NODES];          // dinv[i] + sum_in dinv[s]
__device__ int   g_cur[N_NODES];        // fill cursor == in-degree after fill
__device__ int   g_bkt[N_NODES * BKT];  // per-dst src buckets

// ---------------- streams/events (created at static init) ----------------
static cudaStream_t g_s2 = nullptr, g_s3 = nullptr;
static cudaEvent_t g_evFork = nullptr, g_evJoin = nullptr, g_evW = nullptr, g_evBC = nullptr;
namespace {
struct StreamInit {
    StreamInit() {
        cudaStreamCreateWithFlags(&g_s2, cudaStreamNonBlocking);
        cudaStreamCreateWithFlags(&g_s3, cudaStreamNonBlocking);
        cudaEventCreateWithFlags(&g_evFork, cudaEventDisableTiming);
        cudaEventCreateWithFlags(&g_evJoin, cudaEventDisableTiming);
        cudaEventCreateWithFlags(&g_evW, cudaEventDisableTiming);
        cudaEventCreateWithFlags(&g_evBC, cudaEventDisableTiming);
    }
};
static StreamInit g_si;
}

__device__ __forceinline__ float dinv_of(int cur) {
    return rsqrtf((float)cur + 1.0f);
}
__device__ __forceinline__ float tanh_fast(float x) {
    float r;
    asm("tanh.approx.f32 %0, %1;" : "=f"(r) : "f"(x));
    return r;
}
__device__ __forceinline__ float sig_fast(float x) {
    return 0.5f * tanh_fast(0.5f * x) + 0.5f;
}

// ---------------- graph prologue ----------------
// 4 edges per thread, vectorized loads
__global__ void k_fill(const int* __restrict__ ei) {
    int t = blockIdx.x * blockDim.x + threadIdx.x;
    if (t >= N_EDGES / 4) return;
    int4 s4 = *reinterpret_cast<const int4*>(ei + t * 4);
    int4 d4 = *reinterpret_cast<const int4*>(ei + N_EDGES + t * 4);
    int s[4] = {s4.x, s4.y, s4.z, s4.w};
    int d[4] = {d4.x, d4.y, d4.z, d4.w};
    #pragma unroll
    for (int q = 0; q < 4; q++) {
        int pos = atomicAdd(&g_cur[d[q]], 1);
        if (pos < BKT) g_bkt[d[q] * BKT + pos] = s[q];
    }
}

// one warp per dst node (fp32 — fp16 variants regressed in R9/R12):
// y[i,:] = x[i,:]*dinv[i] + sum_{s in N(i)} x[s,:]*dinv[s]
// u[i]   = dinv[i] + sum dinv[s]
__global__ void k_gather(const float4* __restrict__ x4) {
    int n = (blockIdx.x * blockDim.x + threadIdx.x) >> 5;
    int lane = threadIdx.x & 31;
    if (n >= N_NODES) return;

    const int deg = min(g_cur[n], BKT);
    const int* bkt = g_bkt + (size_t)n * BKT;

    float di = dinv_of(deg);
    float4 xv = __ldg(x4 + (size_t)n * 32 + lane);
    float4 acc = make_float4(xv.x * di, xv.y * di, xv.z * di, xv.w * di);
    float tsum = di;

    for (int c = 0; c < deg; c += 32) {
        int m = min(32, deg - c);
        int idx = 0;
        float dv = 0.0f;
        if (lane < m) {
            idx = __ldg(bkt + c + lane);
            dv = dinv_of(__ldg(g_cur + idx));
        }
        int j = 0;
        for (; j + 4 <= m; j += 4) {
            int s0 = __shfl_sync(0xffffffffu, idx, j);
            int s1 = __shfl_sync(0xffffffffu, idx, j + 1);
            int s2 = __shfl_sync(0xffffffffu, idx, j + 2);
            int s3 = __shfl_sync(0xffffffffu, idx, j + 3);
            float w0 = __shfl_sync(0xffffffffu, dv, j);
            float w1 = __shfl_sync(0xffffffffu, dv, j + 1);
            float w2 = __shfl_sync(0xffffffffu, dv, j + 2);
            float w3 = __shfl_sync(0xffffffffu, dv, j + 3);
            float4 v0 = __ldg(x4 + (size_t)s0 * 32 + lane);
            float4 v1 = __ldg(x4 + (size_t)s1 * 32 + lane);
            float4 v2 = __ldg(x4 + (size_t)s2 * 32 + lane);
            float4 v3 = __ldg(x4 + (size_t)s3 * 32 + lane);
            acc.x = fmaf(v0.x, w0, acc.x); acc.y = fmaf(v0.y, w0, acc.y);
            acc.z = fmaf(v0.z, w0, acc.z); acc.w = fmaf(v0.w, w0, acc.w);
            acc.x = fmaf(v1.x, w1, acc.x); acc.y = fmaf(v1.y, w1, acc.y);
            acc.z = fmaf(v1.z, w1, acc.z); acc.w = fmaf(v1.w, w1, acc.w);
            acc.x = fmaf(v2.x, w2, acc.x); acc.y = fmaf(v2.y, w2, acc.y);
            acc.z = fmaf(v2.z, w2, acc.z); acc.w = fmaf(v2.w, w2, acc.w);
            acc.x = fmaf(v3.x, w3, acc.x); acc.y = fmaf(v3.y, w3, acc.y);
            acc.z = fmaf(v3.z, w3, acc.z); acc.w = fmaf(v3.w, w3, acc.w);
            tsum += w0 + w1 + w2 + w3;
        }
        for (; j < m; j++) {
            int s = __shfl_sync(0xffffffffu, idx, j);
            float ws = __shfl_sync(0xffffffffu, dv, j);
            float4 v = __ldg(x4 + (size_t)s * 32 + lane);
            acc.x = fmaf(v.x, ws, acc.x); acc.y = fmaf(v.y, ws, acc.y);
            acc.z = fmaf(v.z, ws, acc.z); acc.w = fmaf(v.w, ws, acc.w);
            tsum += ws;
        }
    }

    reinterpret_cast<float4*>(g_y)[(size_t)n * 32 + lane] = acc;
    if (lane == 0) g_u[n] = tsum;
}

// ---------------- fused gates GEMM + LSTM evolve ----------------
// Computes W[r, j] = sig(o)*tanh( sig(f)*IW[r,j] + sig(i)*tanh(g) ) where
// gate_g[r, j] = sum_k IW[r,k]*(W_ih+W_hh)[g*H+j, k] + (b_ih+b_hh)[g*H+j].
// Tile: 64 rows x 16 j's x 4 gates (vcol = 4*j_local + gate). Grid (H/16, H/64).
__global__ void k_gates_evolve(const float* __restrict__ IW,
                               const float* __restrict__ W_ih, const float* __restrict__ W_hh,
                               const float* __restrict__ b_ih, const float* __restrict__ b_hh) {
    __shared__ float As[16][68];
    __shared__ float Bs[16][68];
    const int tx = threadIdx.x, ty = threadIdx.y;   // 16 x 16
    const int tid = ty * 16 + tx;
    const int row0 = blockIdx.y * 64;
    const int j0 = blockIdx.x * 16;
    const int K = HID;

    // A load coords (A = IW, 64 rows x 16 k per tile)
    const int ar = tid >> 2;
    const int akq = (tid & 3) * 4;
    const float* Ap = IW + (size_t)(row0 + ar) * K + akq;

    // B load coords: vcol bc = tid>>2 in [0,64): j_local = bc>>2, gate = bc&3
    const int bc = tid >> 2;
    const int bkq = (tid & 3) * 4;
    const int brow = (bc & 3) * HID + (j0 + (bc >> 2));
    const float* Bih = W_ih + (size_t)brow * K + bkq;
    const float* Bhh = W_hh + (size_t)brow * K + bkq;

    float acc[4][4] = {};

    float4 aR = *reinterpret_cast<const float4*>(Ap);
    float4 b1R = *reinterpret_cast<const float4*>(Bih);
    float4 b2R = *reinterpret_cast<const float4*>(Bhh);

    for (int kt = 0; kt < K; kt += 16) {
        As[akq + 0][ar] = aR.x; As[akq + 1][ar] = aR.y;
        As[akq + 2][ar] = aR.z; As[akq + 3][ar] = aR.w;
        Bs[bkq + 0][bc] = b1R.x + b2R.x;
        Bs[bkq + 1][bc] = b1R.y + b2R.y;
        Bs[bkq + 2][bc] = b1R.z + b2R.z;
        Bs[bkq + 3][bc] = b1R.w + b2R.w;
        __syncthreads();

        if (kt + 16 < K) {
            int kn = kt + 16;
            aR  = *reinterpret_cast<const float4*>(Ap + kn);
            b1R = *reinterpret_cast<const float4*>(Bih + kn);
            b2R = *reinterpret_cast<const float4*>(Bhh + kn);
        }

        #pragma unroll
        for (int k = 0; k < 16; k++) {
            float4 a = *reinterpret_cast<const float4*>(&As[k][ty * 4]);
            float4 b = *reinterpret_cast<const float4*>(&Bs[k][tx * 4]);
            float av[4] = {a.x, a.y, a.z, a.w};
            float bv[4] = {b.x, b.y, b.z, b.w};
            #pragma unroll
            for (int i = 0; i < 4; i++)
                #pragma unroll
                for (int j = 0; j < 4; j++)
                    acc[i][j] = fmaf(av[i], bv[j], acc[i][j]);
        }
        __syncthreads();
    }

    // epilogue: LSTM cell in registers, write g_W directly
    const int j = j0 + tx;
    const float bi = b_ih[0 * HID + j] + b_hh[0 * HID + j];
    const float bf = b_ih[1 * HID + j] + b_hh[1 * HID + j];
    const float bg = b_ih[2 * HID + j] + b_hh[2 * HID + j];
    const float bo = b_ih[3 * HID + j] + b_hh[3 * HID + j];
    #pragma unroll
    for (int i = 0; i < 4; i++) {
        int row = row0 + ty * 4 + i;
        float ig = sig_fast(acc[i][0] + bi);
        float fg = sig_fast(acc[i][1] + bf);
        float gg = tanh_fast(acc[i][2] + bg);
        float og = sig_fast(acc[i][3] + bo);
        float c = fg * IW[(size_t)row * HID + j] + ig * gg;
        g_W[(size_t)row * HID + j] = og * tanh_fast(c);
    }
}

// bc[j] = sum_k bp[k] * W[k, j]   (16 blocks x 256 threads, 16-way k split)
__global__ void k_bc(const float* __restrict__ bp) {
    __shared__ float red[16][17];
    int c  = threadIdx.x & 15;
    int kk = threadIdx.x >> 4;
    int col = blockIdx.x * 16 + c;
    float acc = 0.0f;
    #pragma unroll
    for (int t = 0; t < 16; t++) {
        int k = kk + t * 16;
        acc += bp[k] * g_W[k * HID + col];
    }
    red[kk][c] = acc;
    __syncthreads();
    if (kk == 0) {
        float s = 0.0f;
        #pragma unroll
        for (int t = 0; t < 16; t++) s += red[t][c];
        g_bc[col] = s;
    }
}

// ---------------- Wc GEMM: g_Wc = Wp @ g_W  (software-pipelined) ----------------
__global__ void k_wc_gemm(const float* __restrict__ A) {
    __shared__ float As[16][68];
    __shared__ float Bs[16][68];
    const int tx = threadIdx.x, ty = threadIdx.y;
    const int tid = ty * 16 + tx;
    const int row0 = blockIdx.y * 64;
    const int col0 = blockIdx.x * 64;
    const int N = HID, K = HID;

    const int ar = tid >> 2;
    const int akq = (tid & 3) * 4;
    const float* Ap = A + (size_t)(row0 + ar) * K + akq;   // M=128, always in range
    const int bk = tid >> 4;
    const int bcq = (tid & 15) * 4;
    const float* Bp = g_W + (size_t)bk * N + col0 + bcq;

    float acc[4][4] = {};

    float4 aR = *reinterpret_cast<const float4*>(Ap);
    float4 bR = *reinterpret_cast<const float4*>(Bp);

    for (int kt = 0; kt < K; kt += 16) {
        As[akq + 0][ar] = aR.x; As[akq + 1][ar] = aR.y;
        As[akq + 2][ar] = aR.z; As[akq + 3][ar] = aR.w;
        *reinterpret_cast<float4*>(&Bs[bk][bcq]) = bR;
        __syncthreads();

        if (kt + 16 < K) {
            int kn = kt + 16;
            aR = *reinterpret_cast<const float4*>(Ap + kn);
            bR = *reinterpret_cast<const float4*>(Bp + (size_t)kn * N);
        }

        #pragma unroll
        for (int k = 0; k < 16; k++) {
            float4 a = *reinterpret_cast<const float4*>(&As[k][ty * 4]);
            float4 b = *reinterpret_cast<const float4*>(&Bs[k][tx * 4]);
            float av[4] = {a.x, a.y, a.z, a.w};
            float bv[4] = {b.x, b.y, b.z, b.w};
            #pragma unroll
            for (int i = 0; i < 4; i++)
                #pragma unroll
                for (int j = 0; j < 4; j++)
                    acc[i][j] = fmaf(av[i], bv[j], acc[i][j]);
        }
        __syncthreads();
    }

    #pragma unroll
    for (int i = 0; i < 4; i++) {
        int row = row0 + ty * 4 + i;
        int col = col0 + tx * 4;
        float4 v = make_float4(acc[i][0], acc[i][1], acc[i][2], acc[i][3]);
        *reinterpret_cast<float4*>(g_Wc + (size_t)row * HID + col) = v;
    }
}

// ---------------- main GEMM (f32x2 packed FMA, software-pipelined) ----------------
__global__ void k_main_gemm(const float* __restrict__ bgcn, float* __restrict__ out) {
    __shared__ float As[16][132];
    __shared__ float Bs[16][68];
    const int tid = threadIdx.x;           // 256 threads
    const int tx = tid & 15;
    const int ty = tid >> 4;
    const int row0 = blockIdx.y * 128;
    const int col0 = blockIdx.x * 64;
    const int M = N_NODES, N = HID, K = IN_DIM;

    const int ar0 = tid >> 2, ar1 = (tid + 256) >> 2;
    const int akq = (tid & 3) * 4;
    const int arow0 = row0 + ar0, arow1 = row0 + ar1;
    const bool aok0 = arow0 < M, aok1 = arow1 < M;
    const float* Ap0 = g_y + (size_t)(aok0 ? arow0 : 0) * K + akq;
    const float* Ap1 = g_y + (size_t)(aok1 ? arow1 : 0) * K + akq;
    const int bk = tid >> 4;
    const int bcq = (tid & 15) * 4;
    const float* Bp = g_Wc + (size_t)bk * N + col0 + bcq;

    unsigned long long acc2[4][4] = {};

    float4 aR0 = aok0 ? *reinterpret_cast<const float4*>(Ap0) : make_float4(0.f, 0.f, 0.f, 0.f);
    float4 aR1 = aok1 ? *reinterpret_cast<const float4*>(Ap1) : make_float4(0.f, 0.f, 0.f, 0.f);
    float4 bRv = *reinterpret_cast<const float4*>(Bp);

    for (int kt = 0; kt < K; kt += 16) {
        As[akq + 0][ar0] = aR0.x; As[akq + 1][ar0] = aR0.y;
        As[akq + 2][ar0] = aR0.z; As[akq + 3][ar0] = aR0.w;
        As[akq + 0][ar1] = aR1.x; As[akq + 1][ar1] = aR1.y;
        As[akq + 2][ar1] = aR1.z; As[akq + 3][ar1] = aR1.w;
        *reinterpret_cast<float4*>(&Bs[bk][bcq]) = bRv;
        __syncthreads();

        if (kt + 16 < K) {
            int knext = kt + 16;
            aR0 = aok0 ? *reinterpret_cast<const float4*>(Ap0 + knext) : make_float4(0.f, 0.f, 0.f, 0.f);
            aR1 = aok1 ? *reinterpret_cast<const float4*>(Ap1 + knext) : make_float4(0.f, 0.f, 0.f, 0.f);
            bRv = *reinterpret_cast<const float4*>(Bp + (size_t)knext * N);
        }

        #pragma unroll
        for (int k = 0; k < 16; k++) {
            unsigned long long ap[4];
            #pragma unroll
            for (int i2 = 0; i2 < 4; i2++)
                ap[i2] = *reinterpret_cast<const unsigned long long*>(&As[k][ty * 8 + 2 * i2]);
            float4 b = *reinterpret_cast<const float4*>(&Bs[k][tx * 4]);
            unsigned long long bp0, bp1, bp2, bp3;
            asm("mov.b64 %0, {%1, %1};" : "=l"(bp0) : "f"(b.x));
            asm("mov.b64 %0, {%1, %1};" : "=l"(bp1) : "f"(b.y));
            asm("mov.b64 %0, {%1, %1};" : "=l"(bp2) : "f"(b.z));
            asm("mov.b64 %0, {%1, %1};" : "=l"(bp3) : "f"(b.w));
            #pragma unroll
            for (int i2 = 0; i2 < 4; i2++) {
                asm("fma.rn.f32x2 %0, %1, %2, %0;" : "+l"(acc2[i2][0]) : "l"(ap[i2]), "l"(bp0));
                asm("fma.rn.f32x2 %0, %1, %2, %0;" : "+l"(acc2[i2][1]) : "l"(ap[i2]), "l"(bp1));
                asm("fma.rn.f32x2 %0, %1, %2, %0;" : "+l"(acc2[i2][2]) : "l"(ap[i2]), "l"(bp2));
                asm("fma.rn.f32x2 %0, %1, %2, %0;" : "+l"(acc2[i2][3]) : "l"(ap[i2]), "l"(bp3));
            }
        }
        __syncthreads();
    }

    const int col = col0 + tx * 4;
    const float4 bc4 = *reinterpret_cast<const float4*>(g_bc + col);
    const float4 bg4 = *reinterpret_cast<const float4*>(bgcn + col);
    #pragma unroll
    for (int i2 = 0; i2 < 4; i2++) {
        float lo[4], hi[4];
        #pragma unroll
        for (int j = 0; j < 4; j++)
            asm("mov.b64 {%0, %1}, %2;" : "=f"(lo[j]), "=f"(hi[j]) : "l"(acc2[i2][j]));
        #pragma unroll
        for (int h = 0; h < 2; h++) {
            int row = row0 + ty * 8 + 2 * i2 + h;
            if (row >= M) continue;
            float* a = h ? hi : lo;
            float sc = dinv_of(min(g_cur[row], BKT));
            float uu = g_u[row] * sc;
            float4 v;
            v.x = a[0] * sc + bc4.x * uu + bg4.x;
            v.y = a[1] * sc + bc4.y * uu + bg4.y;
            v.z = a[2] * sc + bc4.z * uu + bg4.z;
            v.w = a[3] * sc + bc4.w * uu + bg4.w;
            *reinterpret_cast<float4*>(out + (size_t)row * N + col) = v;
        }
    }
}

// ---------------- launch ----------------
extern "C" void kernel_launch(void* const* d_in, const int* in_sizes, int n_in,
                              void* d_out, int out_size) {
    const float* x    = (const float*)d_in[0];
    const int*   ei   = (const int*)d_in[1];      // jax int64 is silently int32 (x64 disabled)
    const float* Wp   = (const float*)d_in[2];
    const float* bp   = (const float*)d_in[3];
    const float* W_ih = (const float*)d_in[4];
    const float* W_hh = (const float*)d_in[5];
    const float* b_ih = (const float*)d_in[6];
    const float* b_hh = (const float*)d_in[7];
    const float* IW   = (const float*)d_in[8];
    const float* bgcn = (const float*)d_in[9];
    float* out = (float*)d_out;

    int* d_cur; cudaGetSymbolAddress((void**)&d_cur, g_cur);

    dim3 thr(16, 16);

    cudaEventRecord(g_evFork, 0);

    // stream2: fused gates+evolve, then Wc GEMM
    cudaStreamWaitEvent(g_s2, g_evFork, 0);
    k_gates_evolve<<<dim3(HID / 16, HID / 64), thr, 0, g_s2>>>(IW, W_ih, W_hh, b_ih, b_hh);
    cudaEventRecord(g_evW, g_s2);
    k_wc_gemm<<<dim3(HID / 64, IN_DIM / 64), thr, 0, g_s2>>>(Wp);
    cudaEventRecord(g_evJoin, g_s2);

    // stream3: k_bc after evolve, parallel with Wc GEMM (only needs g_W)
    cudaStreamWaitEvent(g_s3, g_evW, 0);
    k_bc<<<16, 256, 0, g_s3>>>(bp);
    cudaEventRecord(g_evBC, g_s3);

    // graph chain on default stream
    cudaMemsetAsync(d_cur, 0, N_NODES * sizeof(int), 0);
    k_fill<<<(N_EDGES / 4 + 255) / 256, 256>>>(ei);
    k_gather<<<(N_NODES * 32 + 255) / 256, 256>>>((const float4*)x);

    // join, then final GEMM
    cudaStreamWaitEvent(0, g_evJoin, 0);
    cudaStreamWaitEvent(0, g_evBC, 0);
    k_main_gemm<<<dim3(HID / 64, (N_NODES + 127) / 128), 256>>>(bgcn, out);
}

// round 14
// speedup vs baseline: 1.5354x; 1.0413x over previous
#include <cuda_runtime.h>
#include <cuda_bf16.h>

#define N_NODES 10000
#define N_EDGES 320000
#define IN_DIM  128
#define HID     256
#define HID4    1024
#define BKT     192      // bucket capacity: deg ~ Poisson(32), 192 = +28 sigma

// ---------------- scratch (static device globals; no allocation) ----------------
__device__ float g_W[HID * HID];        // evolved GCN weight                 [H, H]
__device__ float g_Wc[IN_DIM * HID];    // Wp @ W                             [IN, H]
__device__ float g_bc[HID];             // bp @ W                             [H]
__device__ float g_y[N_NODES * IN_DIM]; // aggregated scaled features        [N, IN]
__device__ float g_u[N_NODES];          // dinv[i] + sum_in dinv[s]
__device__ int   g_cur[N_NODES];        // fill cursor == in-degree after fill
__device__ int   g_bkt[N_NODES * BKT];  // per-dst src buckets

// ---------------- streams/events (created at static init) ----------------
static cudaStream_t g_s2 = nullptr, g_s3 = nullptr;
static cudaEvent_t g_evFork = nullptr, g_evJoin = nullptr, g_evW = nullptr, g_evBC = nullptr;
namespace {
struct StreamInit {
    StreamInit() {
        cudaStreamCreateWithFlags(&g_s2, cudaStreamNonBlocking);
        cudaStreamCreateWithFlags(&g_s3, cudaStreamNonBlocking);
        cudaEventCreateWithFlags(&g_evFork, cudaEventDisableTiming);
        cudaEventCreateWithFlags(&g_evJoin, cudaEventDisableTiming);
        cudaEventCreateWithFlags(&g_evW, cudaEventDisableTiming);
        cudaEventCreateWithFlags(&g_evBC, cudaEventDisableTiming);
    }
};
static StreamInit g_si;
}

__device__ __forceinline__ float dinv_of(int cur) {
    return rsqrtf((float)cur + 1.0f);
}
__device__ __forceinline__ float tanh_fast(float x) {
    float r;
    asm("tanh.approx.f32 %0, %1;" : "=f"(r) : "f"(x));
    return r;
}
__device__ __forceinline__ float sig_fast(float x) {
    return 0.5f * tanh_fast(0.5f * x) + 0.5f;
}

// ---------------- graph prologue ----------------
// 4 edges per thread, vectorized loads
__global__ void k_fill(const int* __restrict__ ei) {
    int t = blockIdx.x * blockDim.x + threadIdx.x;
    if (t >= N_EDGES / 4) return;
    int4 s4 = *reinterpret_cast<const int4*>(ei + t * 4);
    int4 d4 = *reinterpret_cast<const int4*>(ei + N_EDGES + t * 4);
    int s[4] = {s4.x, s4.y, s4.z, s4.w};
    int d[4] = {d4.x, d4.y, d4.z, d4.w};
    #pragma unroll
    for (int q = 0; q < 4; q++) {
        int pos = atomicAdd(&g_cur[d[q]], 1);
        if (pos < BKT) g_bkt[d[q] * BKT + pos] = s[q];
    }
}

// one warp per dst node (fp32 — fp16 variants regressed in R9/R12):
// y[i,:] = x[i,:]*dinv[i] + sum_{s in N(i)} x[s,:]*dinv[s]
// u[i]   = dinv[i] + sum dinv[s]
__global__ void k_gather(const float4* __restrict__ x4) {
    int n = (blockIdx.x * blockDim.x + threadIdx.x) >> 5;
    int lane = threadIdx.x & 31;
    if (n >= N_NODES) return;

    const int deg = min(g_cur[n], BKT);
    const int* bkt = g_bkt + (size_t)n * BKT;

    float di = dinv_of(deg);
    float4 xv = __ldg(x4 + (size_t)n * 32 + lane);
    float4 acc = make_float4(xv.x * di, xv.y * di, xv.z * di, xv.w * di);
    float tsum = di;

    for (int c = 0; c < deg; c += 32) {
        int m = min(32, deg - c);
        int idx = 0;
        float dv = 0.0f;
        if (lane < m) {
            idx = __ldg(bkt + c + lane);
            dv = dinv_of(__ldg(g_cur + idx));
        }
        int j = 0;
        for (; j + 4 <= m; j += 4) {
            int s0 = __shfl_sync(0xffffffffu, idx, j);
            int s1 = __shfl_sync(0xffffffffu, idx, j + 1);
            int s2 = __shfl_sync(0xffffffffu, idx, j + 2);
            int s3 = __shfl_sync(0xffffffffu, idx, j + 3);
            float w0 = __shfl_sync(0xffffffffu, dv, j);
            float w1 = __shfl_sync(0xffffffffu, dv, j + 1);
            float w2 = __shfl_sync(0xffffffffu, dv, j + 2);
            float w3 = __shfl_sync(0xffffffffu, dv, j + 3);
            float4 v0 = __ldg(x4 + (size_t)s0 * 32 + lane);
            float4 v1 = __ldg(x4 + (size_t)s1 * 32 + lane);
            float4 v2 = __ldg(x4 + (size_t)s2 * 32 + lane);
            float4 v3 = __ldg(x4 + (size_t)s3 * 32 + lane);
            acc.x = fmaf(v0.x, w0, acc.x); acc.y = fmaf(v0.y, w0, acc.y);
            acc.z = fmaf(v0.z, w0, acc.z); acc.w = fmaf(v0.w, w0, acc.w);
            acc.x = fmaf(v1.x, w1, acc.x); acc.y = fmaf(v1.y, w1, acc.y);
            acc.z = fmaf(v1.z, w1, acc.z); acc.w = fmaf(v1.w, w1, acc.w);
            acc.x = fmaf(v2.x, w2, acc.x); acc.y = fmaf(v2.y, w2, acc.y);
            acc.z = fmaf(v2.z, w2, acc.z); acc.w = fmaf(v2.w, w2, acc.w);
            acc.x = fmaf(v3.x, w3, acc.x); acc.y = fmaf(v3.y, w3, acc.y);
            acc.z = fmaf(v3.z, w3, acc.z); acc.w = fmaf(v3.w, w3, acc.w);
            tsum += w0 + w1 + w2 + w3;
        }
        for (; j < m; j++) {
            int s = __shfl_sync(0xffffffffu, idx, j);
            float ws = __shfl_sync(0xffffffffu, dv, j);
            float4 v = __ldg(x4 + (size_t)s * 32 + lane);
            acc.x = fmaf(v.x, ws, acc.x); acc.y = fmaf(v.y, ws, acc.y);
            acc.z = fmaf(v.z, ws, acc.z); acc.w = fmaf(v.w, ws, acc.w);
            tsum += ws;
        }
    }

    reinterpret_cast<float4*>(g_y)[(size_t)n * 32 + lane] = acc;
    if (lane == 0) g_u[n] = tsum;
}

// ---------------- fused gates GEMM + LSTM evolve ----------------
// W[r, j] = sig(o)*tanh( sig(f)*IW[r,j] + sig(i)*tanh(g) ), gates from
// IW @ (W_ih+W_hh)^T + (b_ih+b_hh). Tile: 64 rows x 16 j x 4 gates. Grid (H/16, H/64).
__global__ void k_gates_evolve(const float* __restrict__ IW,
                               const float* __restrict__ W_ih, const float* __restrict__ W_hh,
                               const float* __restrict__ b_ih, const float* __restrict__ b_hh) {
    __shared__ float As[16][68];
    __shared__ float Bs[16][68];
    const int tx = threadIdx.x, ty = threadIdx.y;   // 16 x 16
    const int tid = ty * 16 + tx;
    const int row0 = blockIdx.y * 64;
    const int j0 = blockIdx.x * 16;
    const int K = HID;

    const int ar = tid >> 2;
    const int akq = (tid & 3) * 4;
    const float* Ap = IW + (size_t)(row0 + ar) * K + akq;

    const int bc = tid >> 2;
    const int bkq = (tid & 3) * 4;
    const int brow = (bc & 3) * HID + (j0 + (bc >> 2));
    const float* Bih = W_ih + (size_t)brow * K + bkq;
    const float* Bhh = W_hh + (size_t)brow * K + bkq;

    float acc[4][4] = {};

    float4 aR = *reinterpret_cast<const float4*>(Ap);
    float4 b1R = *reinterpret_cast<const float4*>(Bih);
    float4 b2R = *reinterpret_cast<const float4*>(Bhh);

    for (int kt = 0; kt < K; kt += 16) {
        As[akq + 0][ar] = aR.x; As[akq + 1][ar] = aR.y;
        As[akq + 2][ar] = aR.z; As[akq + 3][ar] = aR.w;
        Bs[bkq + 0][bc] = b1R.x + b2R.x;
        Bs[bkq + 1][bc] = b1R.y + b2R.y;
        Bs[bkq + 2][bc] = b1R.z + b2R.z;
        Bs[bkq + 3][bc] = b1R.w + b2R.w;
        __syncthreads();

        if (kt + 16 < K) {
            int kn = kt + 16;
            aR  = *reinterpret_cast<const float4*>(Ap + kn);
            b1R = *reinterpret_cast<const float4*>(Bih + kn);
            b2R = *reinterpret_cast<const float4*>(Bhh + kn);
        }

        #pragma unroll
        for (int k = 0; k < 16; k++) {
            float4 a = *reinterpret_cast<const float4*>(&As[k][ty * 4]);
            float4 b = *reinterpret_cast<const float4*>(&Bs[k][tx * 4]);
            float av[4] = {a.x, a.y, a.z, a.w};
            float bv[4] = {b.x, b.y, b.z, b.w};
            #pragma unroll
            for (int i = 0; i < 4; i++)
                #pragma unroll
                for (int j = 0; j < 4; j++)
                    acc[i][j] = fmaf(av[i], bv[j], acc[i][j]);
        }
        __syncthreads();
    }

    const int j = j0 + tx;
    const float bi = b_ih[0 * HID + j] + b_hh[0 * HID + j];
    const float bf = b_ih[1 * HID + j] + b_hh[1 * HID + j];
    const float bg = b_ih[2 * HID + j] + b_hh[2 * HID + j];
    const float bo = b_ih[3 * HID + j] + b_hh[3 * HID + j];
    #pragma unroll
    for (int i = 0; i < 4; i++) {
        int row = row0 + ty * 4 + i;
        float ig = sig_fast(acc[i][0] + bi);
        float fg = sig_fast(acc[i][1] + bf);
        float gg = tanh_fast(acc[i][2] + bg);
        float og = sig_fast(acc[i][3] + bo);
        float c = fg * IW[(size_t)row * HID + j] + ig * gg;
        g_W[(size_t)row * HID + j] = og * tanh_fast(c);
    }
}

// bc[j] = sum_k bp[k] * W[k, j]   (16 blocks x 256 threads, 16-way k split)
__global__ void k_bc(const float* __restrict__ bp) {
    __shared__ float red[16][17];
    int c  = threadIdx.x & 15;
    int kk = threadIdx.x >> 4;
    int col = blockIdx.x * 16 + c;
    float acc = 0.0f;
    #pragma unroll
    for (int t = 0; t < 16; t++) {
        int k = kk + t * 16;
        acc += bp[k] * g_W[k * HID + col];
    }
    red[kk][c] = acc;
    __syncthreads();
    if (kk == 0) {
        float s = 0.0f;
        #pragma unroll
        for (int t = 0; t < 16; t++) s += red[t][c];
        g_bc[col] = s;
    }
}

// ---------------- Wc GEMM, split-K: g_Wc += Wp[kchunk] @ g_W[kchunk] ----------------
// 32x64 tiles, split-K(4): grid (HID/64=4, IN_DIM/32=4, 4) = 64 blocks.
// g_Wc must be zeroed before. Partials combined with red.global.add.v4.f32.
__global__ void k_wc_gemm(const float* __restrict__ A) {
    __shared__ float As[16][36];
    __shared__ float Bs[16][68];
    const int tid = threadIdx.x;            // 256 threads
    const int tx = tid & 15;
    const int ty = tid >> 4;                // 0..15 -> 2 rows each
    const int row0 = blockIdx.y * 32;
    const int col0 = blockIdx.x * 64;
    const int kbase = blockIdx.z * 64;
    const int N = HID, K = HID;

    // A loads: 32x16 tile = 128 float4, threads 0..127
    const int ar = (tid & 127) >> 2;
    const int akq = (tid & 3) * 4;
    const bool aload = tid < 128;
    const float* Ap = A + (size_t)(row0 + ar) * K + kbase + akq;
    // B loads: 16x64 tile = 256 float4, all threads
    const int bk = tid >> 4;
    const int bcq = (tid & 15) * 4;
    const float* Bp = g_W + (size_t)(kbase + bk) * N + col0 + bcq;

    float acc[2][4] = {};

    float4 aR = aload ? *reinterpret_cast<const float4*>(Ap) : make_float4(0.f, 0.f, 0.f, 0.f);
    float4 bR = *reinterpret_cast<const float4*>(Bp);

    #pragma unroll
    for (int kt = 0; kt < 64; kt += 16) {
        if (aload) {
            As[akq + 0][ar] = aR.x; As[akq + 1][ar] = aR.y;
            As[akq + 2][ar] = aR.z; As[akq + 3][ar] = aR.w;
        }
        *reinterpret_cast<float4*>(&Bs[bk][bcq]) = bR;
        __syncthreads();

        if (kt + 16 < 64) {
            int kn = kt + 16;
            if (aload) aR = *reinterpret_cast<const float4*>(Ap + kn);
            bR = *reinterpret_cast<const float4*>(Bp + (size_t)kn * N);
        }

        #pragma unroll
        for (int k = 0; k < 16; k++) {
            float a0 = As[k][ty * 2];
            float a1 = As[k][ty * 2 + 1];
            float4 b = *reinterpret_cast<const float4*>(&Bs[k][tx * 4]);
            acc[0][0] = fmaf(a0, b.x, acc[0][0]); acc[0][1] = fmaf(a0, b.y, acc[0][1]);
            acc[0][2] = fmaf(a0, b.z, acc[0][2]); acc[0][3] = fmaf(a0, b.w, acc[0][3]);
            acc[1][0] = fmaf(a1, b.x, acc[1][0]); acc[1][1] = fmaf(a1, b.y, acc[1][1]);
            acc[1][2] = fmaf(a1, b.z, acc[1][2]); acc[1][3] = fmaf(a1, b.w, acc[1][3]);
        }
        __syncthreads();
    }

    #pragma unroll
    for (int i = 0; i < 2; i++) {
        int row = row0 + ty * 2 + i;
        float* dst = g_Wc + (size_t)row * HID + col0 + tx * 4;
        asm volatile("red.global.add.v4.f32 [%0], {%1,%2,%3,%4};"
                     :: "l"(dst), "f"(acc[i][0]), "f"(acc[i][1]), "f"(acc[i][2]), "f"(acc[i][3])
                     : "memory");
    }
}

// ---------------- main GEMM (f32x2 packed FMA, software-pipelined) ----------------
__global__ void k_main_gemm(const float* __restrict__ bgcn, float* __restrict__ out) {
    __shared__ float As[16][132];
    __shared__ float Bs[16][68];
    const int tid = threadIdx.x;           // 256 threads
    const int tx = tid & 15;
    const int ty = tid >> 4;
    const int row0 = blockIdx.y * 128;
    const int col0 = blockIdx.x * 64;
    const int M = N_NODES, N = HID, K = IN_DIM;

    const int ar0 = tid >> 2, ar1 = (tid + 256) >> 2;
    const int akq = (tid & 3) * 4;
    const int arow0 = row0 + ar0, arow1 = row0 + ar1;
    const bool aok0 = arow0 < M, aok1 = arow1 < M;
    const float* Ap0 = g_y + (size_t)(aok0 ? arow0 : 0) * K + akq;
    const float* Ap1 = g_y + (size_t)(aok1 ? arow1 : 0) * K + akq;
    const int bk = tid >> 4;
    const int bcq = (tid & 15) * 4;
    const float* Bp = g_Wc + (size_t)bk * N + col0 + bcq;

    unsigned long long acc2[4][4] = {};

    float4 aR0 = aok0 ? *reinterpret_cast<const float4*>(Ap0) : make_float4(0.f, 0.f, 0.f, 0.f);
    float4 aR1 = aok1 ? *reinterpret_cast<const float4*>(Ap1) : make_float4(0.f, 0.f, 0.f, 0.f);
    float4 bRv = *reinterpret_cast<const float4*>(Bp);

    for (int kt = 0; kt < K; kt += 16) {
        As[akq + 0][ar0] = aR0.x; As[akq + 1][ar0] = aR0.y;
        As[akq + 2][ar0] = aR0.z; As[akq + 3][ar0] = aR0.w;
        As[akq + 0][ar1] = aR1.x; As[akq + 1][ar1] = aR1.y;
        As[akq + 2][ar1] = aR1.z; As[akq + 3][ar1] = aR1.w;
        *reinterpret_cast<float4*>(&Bs[bk][bcq]) = bRv;
        __syncthreads();

        if (kt + 16 < K) {
            int knext = kt + 16;
            aR0 = aok0 ? *reinterpret_cast<const float4*>(Ap0 + knext) : make_float4(0.f, 0.f, 0.f, 0.f);
            aR1 = aok1 ? *reinterpret_cast<const float4*>(Ap1 + knext) : make_float4(0.f, 0.f, 0.f, 0.f);
            bRv = *reinterpret_cast<const float4*>(Bp + (size_t)knext * N);
        }

        #pragma unroll
        for (int k = 0; k < 16; k++) {
            unsigned long long ap[4];
            #pragma unroll
            for (int i2 = 0; i2 < 4; i2++)
                ap[i2] = *reinterpret_cast<const unsigned long long*>(&As[k][ty * 8 + 2 * i2]);
            float4 b = *reinterpret_cast<const float4*>(&Bs[k][tx * 4]);
            unsigned long long bp0, bp1, bp2, bp3;
            asm("mov.b64 %0, {%1, %1};" : "=l"(bp0) : "f"(b.x));
            asm("mov.b64 %0, {%1, %1};" : "=l"(bp1) : "f"(b.y));
            asm("mov.b64 %0, {%1, %1};" : "=l"(bp2) : "f"(b.z));
            asm("mov.b64 %0, {%1, %1};" : "=l"(bp3) : "f"(b.w));
            #pragma unroll
            for (int i2 = 0; i2 < 4; i2++) {
                asm("fma.rn.f32x2 %0, %1, %2, %0;" : "+l"(acc2[i2][0]) : "l"(ap[i2]), "l"(bp0));
                asm("fma.rn.f32x2 %0, %1, %2, %0;" : "+l"(acc2[i2][1]) : "l"(ap[i2]), "l"(bp1));
                asm("fma.rn.f32x2 %0, %1, %2, %0;" : "+l"(acc2[i2][2]) : "l"(ap[i2]), "l"(bp2));
                asm("fma.rn.f32x2 %0, %1, %2, %0;" : "+l"(acc2[i2][3]) : "l"(ap[i2]), "l"(bp3));
            }
        }
        __syncthreads();
    }

    const int col = col0 + tx * 4;
    const float4 bc4 = *reinterpret_cast<const float4*>(g_bc + col);
    const float4 bg4 = *reinterpret_cast<const float4*>(bgcn + col);
    #pragma unroll
    for (int i2 = 0; i2 < 4; i2++) {
        float lo[4], hi[4];
        #pragma unroll
        for (int j = 0; j < 4; j++)
            asm("mov.b64 {%0, %1}, %2;" : "=f"(lo[j]), "=f"(hi[j]) : "l"(acc2[i2][j]));
        #pragma unroll
        for (int h = 0; h < 2; h++) {
            int row = row0 + ty * 8 + 2 * i2 + h;
            if (row >= M) continue;
            float* a = h ? hi : lo;
            float sc = dinv_of(min(g_cur[row], BKT));
            float uu = g_u[row] * sc;
            float4 v;
            v.x = a[0] * sc + bc4.x * uu + bg4.x;
            v.y = a[1] * sc + bc4.y * uu + bg4.y;
            v.z = a[2] * sc + bc4.z * uu + bg4.z;
            v.w = a[3] * sc + bc4.w * uu + bg4.w;
            *reinterpret_cast<float4*>(out + (size_t)row * N + col) = v;
        }
    }
}

// ---------------- launch ----------------
extern "C" void kernel_launch(void* const* d_in, const int* in_sizes, int n_in,
                              void* d_out, int out_size) {
    const float* x    = (const float*)d_in[0];
    const int*   ei   = (const int*)d_in[1];      // jax int64 is silently int32 (x64 disabled)
    const float* Wp   = (const float*)d_in[2];
    const float* bp   = (const float*)d_in[3];
    const float* W_ih = (const float*)d_in[4];
    const float* W_hh = (const float*)d_in[5];
    const float* b_ih = (const float*)d_in[6];
    const float* b_hh = (const float*)d_in[7];
    const float* IW   = (const float*)d_in[8];
    const float* bgcn = (const float*)d_in[9];
    float* out = (float*)d_out;

    int*   d_cur; cudaGetSymbolAddress((void**)&d_cur, g_cur);
    float* d_Wc;  cudaGetSymbolAddress((void**)&d_Wc, g_Wc);

    dim3 thr(16, 16);

    cudaEventRecord(g_evFork, 0);

    // stream2: zero Wc, fused gates+evolve, then split-K Wc GEMM
    cudaStreamWaitEvent(g_s2, g_evFork, 0);
    cudaMemsetAsync(d_Wc, 0, IN_DIM * HID * sizeof(float), g_s2);
    k_gates_evolve<<<dim3(HID / 16, HID / 64), thr, 0, g_s2>>>(IW, W_ih, W_hh, b_ih, b_hh);
    cudaEventRecord(g_evW, g_s2);
    k_wc_gemm<<<dim3(HID / 64, IN_DIM / 32, 4), 256, 0, g_s2>>>(Wp);
    cudaEventRecord(g_evJoin, g_s2);

    // stream3: k_bc after evolve, parallel with Wc GEMM (only needs g_W)
    cudaStreamWaitEvent(g_s3, g_evW, 0);
    k_bc<<<16, 256, 0, g_s3>>>(bp);
    cudaEventRecord(g_evBC, g_s3);

    // graph chain on default stream
    cudaMemsetAsync(d_cur, 0, N_NODES * sizeof(int), 0);
    k_fill<<<(N_EDGES / 4 + 255) / 256, 256>>>(ei);
    k_gather<<<(N_NODES * 32 + 255) / 256, 256>>>((const float4*)x);

    // join, then final GEMM
    cudaStreamWaitEvent(0, g_evJoin, 0);
    cudaStreamWaitEvent(0, g_evBC, 0);
    k_main_gemm<<<dim3(HID / 64, (N_NODES + 127) / 128), 256>>>(bgcn, out);
}

// round 16
// speedup vs baseline: 1.5904x; 1.0358x over previous
#include <cuda_runtime.h>
#include <cuda_bf16.h>

#define N_NODES 10000
#define N_EDGES 320000
#define IN_DIM  128
#define HID     256
#define HID4    1024
#define NSH     4        // cursor shards per node
#define SUBCAP  64       // per-shard bucket capacity: Poisson(8), 64 = +20 sigma

// ---------------- scratch (static device globals; no allocation) ----------------
__device__ float g_W[HID * HID];        // evolved GCN weight                 [H, H]
__device__ float g_Wc[IN_DIM * HID];    // Wp @ W                             [IN, H]
__device__ float g_bc[HID];             // bp @ W                             [H]
__device__ float g_y[N_NODES * IN_DIM]; // aggregated scaled features        [N, IN]
__device__ float g_u[N_NODES];          // dinv[i] + sum_in dinv[s]
__device__ float g_dinv[N_NODES];       // rsqrt(deg+1), written by gather
__device__ int   g_cur[N_NODES * NSH];  // sharded fill cursors (zeroed at load, re-zeroed per call)
__device__ int   g_bkt[N_NODES * NSH * SUBCAP];  // per-dst sharded src buckets

// ---------------- streams/events (created at static init) ----------------
static cudaStream_t g_s2 = nullptr, g_s3 = nullptr;
static cudaEvent_t g_evFork = nullptr, g_evJoin = nullptr, g_evW = nullptr;
static cudaEvent_t g_evBC = nullptr, g_evG = nullptr, g_evCR = nullptr;
namespace {
struct StreamInit {
    StreamInit() {
        cudaStreamCreateWithFlags(&g_s2, cudaStreamNonBlocking);
        cudaStreamCreateWithFlags(&g_s3, cudaStreamNonBlocking);
        cudaEventCreateWithFlags(&g_evFork, cudaEventDisableTiming);
        cudaEventCreateWithFlags(&g_evJoin, cudaEventDisableTiming);
        cudaEventCreateWithFlags(&g_evW, cudaEventDisableTiming);
        cudaEventCreateWithFlags(&g_evBC, cudaEventDisableTiming);
        cudaEventCreateWithFlags(&g_evG, cudaEventDisableTiming);
        cudaEventCreateWithFlags(&g_evCR, cudaEventDisableTiming);
    }
};
static StreamInit g_si;
}

__device__ __forceinline__ float tanh_fast(float x) {
    float r;
    asm("tanh.approx.f32 %0, %1;" : "=f"(r) : "f"(x));
    return r;
}
__device__ __forceinline__ float sig_fast(float x) {
    return 0.5f * tanh_fast(0.5f * x) + 0.5f;
}
// total degree from a node's 4 shard cursors (clamped)
__device__ __forceinline__ int deg_of(int n) {
    const int4 c = *reinterpret_cast<const int4*>(g_cur + n * NSH);
    return min(c.x, SUBCAP) + min(c.y, SUBCAP) + min(c.z, SUBCAP) + min(c.w, SUBCAP);
}

// ---------------- graph prologue ----------------
// 4 edges per thread; shard = position within the quad (uniformly distributes
// any node's edges over its 4 cursors -> 4x less same-address atomic collision)
__global__ void k_fill(const int* __restrict__ ei) {
    int t = blockIdx.x * blockDim.x + threadIdx.x;
    if (t >= N_EDGES / 4) return;
    int4 s4 = *reinterpret_cast<const int4*>(ei + t * 4);
    int4 d4 = *reinterpret_cast<const int4*>(ei + N_EDGES + t * 4);
    int s[4] = {s4.x, s4.y, s4.z, s4.w};
    int d[4] = {d4.x, d4.y, d4.z, d4.w};
    #pragma unroll
    for (int q = 0; q < 4; q++) {
        int slot = d[q] * NSH + q;
        int pos = atomicAdd(&g_cur[slot], 1);
        if (pos < SUBCAP) g_bkt[slot * SUBCAP + pos] = s[q];
    }
}

// one warp per dst node:
// y[i,:] = x[i,:]*dinv[i] + sum_{s in N(i)} x[s,:]*dinv[s]
// u[i]   = dinv[i] + sum dinv[s];  also stores dinv[i] for the GEMM epilogue
__global__ void k_gather(const float4* __restrict__ x4) {
    int n = (blockIdx.x * blockDim.x + threadIdx.x) >> 5;
    int lane = threadIdx.x & 31;
    if (n >= N_NODES) return;

    const int4 c4 = *reinterpret_cast<const int4*>(g_cur + n * NSH);
    const int cs[4] = {min(c4.x, SUBCAP), min(c4.y, SUBCAP), min(c4.z, SUBCAP), min(c4.w, SUBCAP)};
    const int deg = cs[0] + cs[1] + cs[2] + cs[3];

    float di = rsqrtf((float)deg + 1.0f);
    float4 xv = __ldg(x4 + (size_t)n * 32 + lane);
    float4 acc = make_float4(xv.x * di, xv.y * di, xv.z * di, xv.w * di);
    float tsum = di;

    #pragma unroll
    for (int sh = 0; sh < NSH; sh++) {
        const int* bkt = g_bkt + ((size_t)n * NSH + sh) * SUBCAP;
        const int mt = cs[sh];
        for (int c = 0; c < mt; c += 32) {
            int m = min(32, mt - c);
            int idx = 0;
            float dv = 0.0f;
            if (lane < m) {
                idx = __ldg(bkt + c + lane);
                dv = rsqrtf((float)deg_of(idx) + 1.0f);
            }
            int j = 0;
            for (; j + 4 <= m; j += 4) {
                int s0 = __shfl_sync(0xffffffffu, idx, j);
                int s1 = __shfl_sync(0xffffffffu, idx, j + 1);
                int s2 = __shfl_sync(0xffffffffu, idx, j + 2);
                int s3 = __shfl_sync(0xffffffffu, idx, j + 3);
                float w0 = __shfl_sync(0xffffffffu, dv, j);
                float w1 = __shfl_sync(0xffffffffu, dv, j + 1);
                float w2 = __shfl_sync(0xffffffffu, dv, j + 2);
                float w3 = __shfl_sync(0xffffffffu, dv, j + 3);
                float4 v0 = __ldg(x4 + (size_t)s0 * 32 + lane);
                float4 v1 = __ldg(x4 + (size_t)s1 * 32 + lane);
                float4 v2 = __ldg(x4 + (size_t)s2 * 32 + lane);
                float4 v3 = __ldg(x4 + (size_t)s3 * 32 + lane);
                acc.x = fmaf(v0.x, w0, acc.x); acc.y = fmaf(v0.y, w0, acc.y);
                acc.z = fmaf(v0.z, w0, acc.z); acc.w = fmaf(v0.w, w0, acc.w);
                acc.x = fmaf(v1.x, w1, acc.x); acc.y = fmaf(v1.y, w1, acc.y);
                acc.z = fmaf(v1.z, w1, acc.z); acc.w = fmaf(v1.w, w1, acc.w);
                acc.x = fmaf(v2.x, w2, acc.x); acc.y = fmaf(v2.y, w2, acc.y);
                acc.z = fmaf(v2.z, w2, acc.z); acc.w = fmaf(v2.w, w2, acc.w);
                acc.x = fmaf(v3.x, w3, acc.x); acc.y = fmaf(v3.y, w3, acc.y);
                acc.z = fmaf(v3.z, w3, acc.z); acc.w = fmaf(v3.w, w3, acc.w);
                tsum += w0 + w1 + w2 + w3;
            }
            for (; j < m; j++) {
                int s = __shfl_sync(0xffffffffu, idx, j);
                float ws = __shfl_sync(0xffffffffu, dv, j);
                float4 v = __ldg(x4 + (size_t)s * 32 + lane);
                acc.x = fmaf(v.x, ws, acc.x); acc.y = fmaf(v.y, ws, acc.y);
                acc.z = fmaf(v.z, ws, acc.z); acc.w = fmaf(v.w, ws, acc.w);
                tsum += ws;
            }
        }
    }

    reinterpret_cast<float4*>(g_y)[(size_t)n * 32 + lane] = acc;
    if (lane == 0) { g_u[n] = tsum; g_dinv[n] = di; }
}

// ---------------- fused gates GEMM + LSTM evolve ----------------
// W[r, j] = sig(o)*tanh( sig(f)*IW[r,j] + sig(i)*tanh(g) ), gates from
// IW @ (W_ih+W_hh)^T + (b_ih+b_hh). Tile: 64 rows x 16 j x 4 gates. Grid (H/16, H/64).
__global__ void k_gates_evolve(const float* __restrict__ IW,
                               const float* __restrict__ W_ih, const float* __restrict__ W_hh,
                               const float* __restrict__ b_ih, const float* __restrict__ b_hh) {
    __shared__ float As[16][68];
    __shared__ float Bs[16][68];
    const int tx = threadIdx.x, ty = threadIdx.y;   // 16 x 16
    const int tid = ty * 16 + tx;
    const int row0 = blockIdx.y * 64;
    const int j0 = blockIdx.x * 16;
    const int K = HID;

    const int ar = tid >> 2;
    const int akq = (tid & 3) * 4;
    const float* Ap = IW + (size_t)(row0 + ar) * K + akq;

    const int bc = tid >> 2;
    const int bkq = (tid & 3) * 4;
    const int brow = (bc & 3) * HID + (j0 + (bc >> 2));
    const float* Bih = W_ih + (size_t)brow * K + bkq;
    const float* Bhh = W_hh + (size_t)brow * K + bkq;

    float acc[4][4] = {};

    float4 aR = *reinterpret_cast<const float4*>(Ap);
    float4 b1R = *reinterpret_cast<const float4*>(Bih);
    float4 b2R = *reinterpret_cast<const float4*>(Bhh);

    for (int kt = 0; kt < K; kt += 16) {
        As[akq + 0][ar] = aR.x; As[akq + 1][ar] = aR.y;
        As[akq + 2][ar] = aR.z; As[akq + 3][ar] = aR.w;
        Bs[bkq + 0][bc] = b1R.x + b2R.x;
        Bs[bkq + 1][bc] = b1R.y + b2R.y;
        Bs[bkq + 2][bc] = b1R.z + b2R.z;
        Bs[bkq + 3][bc] = b1R.w + b2R.w;
        __syncthreads();

        if (kt + 16 < K) {
            int kn = kt + 16;
            aR  = *reinterpret_cast<const float4*>(Ap + kn);
            b1R = *reinterpret_cast<const float4*>(Bih + kn);
            b2R = *reinterpret_cast<const float4*>(Bhh + kn);
        }

        #pragma unroll
        for (int k = 0; k < 16; k++) {
            float4 a = *reinterpret_cast<const float4*>(&As[k][ty * 4]);
            float4 b = *reinterpret_cast<const float4*>(&Bs[k][tx * 4]);
            float av[4] = {a.x, a.y, a.z, a.w};
            float bv[4] = {b.x, b.y, b.z, b.w};
            #pragma unroll
            for (int i = 0; i < 4; i++)
                #pragma unroll
                for (int j = 0; j < 4; j++)
                    acc[i][j] = fmaf(av[i], bv[j], acc[i][j]);
        }
        __syncthreads();
    }

    const int j = j0 + tx;
    const float bi = b_ih[0 * HID + j] + b_hh[0 * HID + j];
    const float bf = b_ih[1 * HID + j] + b_hh[1 * HID + j];
    const float bg = b_ih[2 * HID + j] + b_hh[2 * HID + j];
    const float bo = b_ih[3 * HID + j] + b_hh[3 * HID + j];
    #pragma unroll
    for (int i = 0; i < 4; i++) {
        int row = row0 + ty * 4 + i;
        float ig = sig_fast(acc[i][0] + bi);
        float fg = sig_fast(acc[i][1] + bf);
        float gg = tanh_fast(acc[i][2] + bg);
        float og = sig_fast(acc[i][3] + bo);
        float c = fg * IW[(size_t)row * HID + j] + ig * gg;
        g_W[(size_t)row * HID + j] = og * tanh_fast(c);
    }
}

// bc[j] = sum_k bp[k] * W[k, j]   (16 blocks x 256 threads, 16-way k split)
__global__ void k_bc(const float* __restrict__ bp) {
    __shared__ float red[16][17];
    int c  = threadIdx.x & 15;
    int kk = threadIdx.x >> 4;
    int col = blockIdx.x * 16 + c;
    float acc = 0.0f;
    #pragma unroll
    for (int t = 0; t < 16; t++) {
        int k = kk + t * 16;
        acc += bp[k] * g_W[k * HID + col];
    }
    red[kk][c] = acc;
    __syncthreads();
    if (kk == 0) {
        float s = 0.0f;
        #pragma unroll
        for (int t = 0; t < 16; t++) s += red[t][c];
        g_bc[col] = s;
    }
}

// ---------------- Wc GEMM, split-K: g_Wc += Wp[kchunk] @ g_W[kchunk] ----------------
// 32x64 tiles, split-K(4): grid (HID/64=4, IN_DIM/32=4, 4) = 64 blocks.
__global__ void k_wc_gemm(const float* __restrict__ A) {
    __shared__ float As[16][36];
    __shared__ float Bs[16][68];
    const int tid = threadIdx.x;            // 256 threads
    const int tx = tid & 15;
    const int ty = tid >> 4;                // 0..15 -> 2 rows each
    const int row0 = blockIdx.y * 32;
    const int col0 = blockIdx.x * 64;
    const int kbase = blockIdx.z * 64;
    const int N = HID, K = HID;

    const int ar = (tid & 127) >> 2;
    const int akq = (tid & 3) * 4;
    const bool aload = tid < 128;
    const float* Ap = A + (size_t)(row0 + ar) * K + kbase + akq;
    const int bk = tid >> 4;
    const int bcq = (tid & 15) * 4;
    const float* Bp = g_W + (size_t)(kbase + bk) * N + col0 + bcq;

    float acc[2][4] = {};

    float4 aR = aload ? *reinterpret_cast<const float4*>(Ap) : make_float4(0.f, 0.f, 0.f, 0.f);
    float4 bR = *reinterpret_cast<const float4*>(Bp);

    #pragma unroll
    for (int kt = 0; kt < 64; kt += 16) {
        if (aload) {
            As[akq + 0][ar] = aR.x; As[akq + 1][ar] = aR.y;
            As[akq + 2][ar] = aR.z; As[akq + 3][ar] = aR.w;
        }
        *reinterpret_cast<float4*>(&Bs[bk][bcq]) = bR;
        __syncthreads();

        if (kt + 16 < 64) {
            int kn = kt + 16;
            if (aload) aR = *reinterpret_cast<const float4*>(Ap + kn);
            bR = *reinterpret_cast<const float4*>(Bp + (size_t)kn * N);
        }

        #pragma unroll
        for (int k = 0; k < 16; k++) {
            float a0 = As[k][ty * 2];
            float a1 = As[k][ty * 2 + 1];
            float4 b = *reinterpret_cast<const float4*>(&Bs[k][tx * 4]);
            acc[0][0] = fmaf(a0, b.x, acc[0][0]); acc[0][1] = fmaf(a0, b.y, acc[0][1]);
            acc[0][2] = fmaf(a0, b.z, acc[0][2]); acc[0][3] = fmaf(a0, b.w, acc[0][3]);
            acc[1][0] = fmaf(a1, b.x, acc[1][0]); acc[1][1] = fmaf(a1, b.y, acc[1][1]);
            acc[1][2] = fmaf(a1, b.z, acc[1][2]); acc[1][3] = fmaf(a1, b.w, acc[1][3]);
        }
        __syncthreads();
    }

    #pragma unroll
    for (int i = 0; i < 2; i++) {
        int row = row0 + ty * 2 + i;
        float* dst = g_Wc + (size_t)row * HID + col0 + tx * 4;
        asm volatile("red.global.add.v4.f32 [%0], {%1,%2,%3,%4};"
                     :: "l"(dst), "f"(acc[i][0]), "f"(acc[i][1]), "f"(acc[i][2]), "f"(acc[i][3])
                     : "memory");
    }
}

// ---------------- main GEMM (f32x2 packed FMA, software-pipelined) ----------------
__global__ void k_main_gemm(const float* __restrict__ bgcn, float* __restrict__ out) {
    __shared__ float As[16][132];
    __shared__ float Bs[16][68];
    const int tid = threadIdx.x;           // 256 threads
    const int tx = tid & 15;
    const int ty = tid >> 4;
    const int row0 = blockIdx.y * 128;
    const int col0 = blockIdx.x * 64;
    const int M = N_NODES, N = HID, K = IN_DIM;

    const int ar0 = tid >> 2, ar1 = (tid + 256) >> 2;
    const int akq = (tid & 3) * 4;
    const int arow0 = row0 + ar0, arow1 = row0 + ar1;
    const bool aok0 = arow0 < M, aok1 = arow1 < M;
    const float* Ap0 = g_y + (size_t)(aok0 ? arow0 : 0) * K + akq;
    const float* Ap1 = g_y + (size_t)(aok1 ? arow1 : 0) * K + akq;
    const int bk = tid >> 4;
    const int bcq = (tid & 15) * 4;
    const float* Bp = g_Wc + (size_t)bk * N + col0 + bcq;

    unsigned long long acc2[4][4] = {};

    float4 aR0 = aok0 ? *reinterpret_cast<const float4*>(Ap0) : make_float4(0.f, 0.f, 0.f, 0.f);
    float4 aR1 = aok1 ? *reinterpret_cast<const float4*>(Ap1) : make_float4(0.f, 0.f, 0.f, 0.f);
    float4 bRv = *reinterpret_cast<const float4*>(Bp);

    for (int kt = 0; kt < K; kt += 16) {
        As[akq + 0][ar0] = aR0.x; As[akq + 1][ar0] = aR0.y;
        As[akq + 2][ar0] = aR0.z; As[akq + 3][ar0] = aR0.w;
        As[akq + 0][ar1] = aR1.x; As[akq + 1][ar1] = aR1.y;
        As[akq + 2][ar1] = aR1.z; As[akq + 3][ar1] = aR1.w;
        *reinterpret_cast<float4*>(&Bs[bk][bcq]) = bRv;
        __syncthreads();

        if (kt + 16 < K) {
            int knext = kt + 16;
            aR0 = aok0 ? *reinterpret_cast<const float4*>(Ap0 + knext) : make_float4(0.f, 0.f, 0.f, 0.f);
            aR1 = aok1 ? *reinterpret_cast<const float4*>(Ap1 + knext) : make_float4(0.f, 0.f, 0.f, 0.f);
            bRv = *reinterpret_cast<const float4*>(Bp + (size_t)knext * N);
        }

        #pragma unroll
        for (int k = 0; k < 16; k++) {
            unsigned long long ap[4];
            #pragma unroll
            for (int i2 = 0; i2 < 4; i2++)
                ap[i2] = *reinterpret_cast<const unsigned long long*>(&As[k][ty * 8 + 2 * i2]);
            float4 b = *reinterpret_cast<const float4*>(&Bs[k][tx * 4]);
            unsigned long long bp0, bp1, bp2, bp3;
            asm("mov.b64 %0, {%1, %1};" : "=l"(bp0) : "f"(b.x));
            asm("mov.b64 %0, {%1, %1};" : "=l"(bp1) : "f"(b.y));
            asm("mov.b64 %0, {%1, %1};" : "=l"(bp2) : "f"(b.z));
            asm("mov.b64 %0, {%1, %1};" : "=l"(bp3) : "f"(b.w));
            #pragma unroll
            for (int i2 = 0; i2 < 4; i2++) {
                asm("fma.rn.f32x2 %0, %1, %2, %0;" : "+l"(acc2[i2][0]) : "l"(ap[i2]), "l"(bp0));
                asm("fma.rn.f32x2 %0, %1, %2, %0;" : "+l"(acc2[i2][1]) : "l"(ap[i2]), "l"(bp1));
                asm("fma.rn.f32x2 %0, %1, %2, %0;" : "+l"(acc2[i2][2]) : "l"(ap[i2]), "l"(bp2));
                asm("fma.rn.f32x2 %0, %1, %2, %0;" : "+l"(acc2[i2][3]) : "l"(ap[i2]), "l"(bp3));
            }
        }
        __syncthreads();
    }

    const int col = col0 + tx * 4;
    const float4 bc4 = *reinterpret_cast<const float4*>(g_bc + col);
    const float4 bg4 = *reinterpret_cast<const float4*>(bgcn + col);
    #pragma unroll
    for (int i2 = 0; i2 < 4; i2++) {
        float lo[4], hi[4];
        #pragma unroll
        for (int j = 0; j < 4; j++)
            asm("mov.b64 {%0, %1}, %2;" : "=f"(lo[j]), "=f"(hi[j]) : "l"(acc2[i2][j]));
        #pragma unroll
        for (int h = 0; h < 2; h++) {
            int row = row0 + ty * 8 + 2 * i2 + h;
            if (row >= M) continue;
            float* a = h ? hi : lo;
            float sc = g_dinv[row];
            float uu = g_u[row] * sc;
            float4 v;
            v.x = a[0] * sc + bc4.x * uu + bg4.x;
            v.y = a[1] * sc + bc4.y * uu + bg4.y;
            v.z = a[2] * sc + bc4.z * uu + bg4.z;
            v.w = a[3] * sc + bc4.w * uu + bg4.w;
            *reinterpret_cast<float4*>(out + (size_t)row * N + col) = v;
        }
    }
}

// ---------------- launch ----------------
extern "C" void kernel_launch(void* const* d_in, const int* in_sizes, int n_in,
                              void* d_out, int out_size) {
    const float* x    = (const float*)d_in[0];
    const int*   ei   = (const int*)d_in[1];      // jax int64 is silently int32 (x64 disabled)
    const float* Wp   = (const float*)d_in[2];
    const float* bp   = (const float*)d_in[3];
    const float* W_ih = (const float*)d_in[4];
    const float* W_hh = (const float*)d_in[5];
    const float* b_ih = (const float*)d_in[6];
    const float* b_hh = (const float*)d_in[7];
    const float* IW   = (const float*)d_in[8];
    const float* bgcn = (const float*)d_in[9];
    float* out = (float*)d_out;

    int*   d_cur; cudaGetSymbolAddress((void**)&d_cur, g_cur);
    float* d_Wc;  cudaGetSymbolAddress((void**)&d_Wc, g_Wc);

    dim3 thr(16, 16);

    cudaEventRecord(g_evFork, 0);

    // stream2: zero Wc, fused gates+evolve, then split-K Wc GEMM
    cudaStreamWaitEvent(g_s2, g_evFork, 0);
    cudaMemsetAsync(d_Wc, 0, IN_DIM * HID * sizeof(float), g_s2);
    k_gates_evolve<<<dim3(HID / 16, HID / 64), thr, 0, g_s2>>>(IW, W_ih, W_hh, b_ih, b_hh);
    cudaEventRecord(g_evW, g_s2);
    k_wc_gemm<<<dim3(HID / 64, IN_DIM / 32, 4), 256, 0, g_s2>>>(Wp);
    cudaEventRecord(g_evJoin, g_s2);

    // stream3: k_bc after evolve, parallel with Wc GEMM (only needs g_W)
    cudaStreamWaitEvent(g_s3, g_evW, 0);
    k_bc<<<16, 256, 0, g_s3>>>(bp);
    cudaEventRecord(g_evBC, g_s3);

    // graph chain on default stream — cursors already zero (module load / prior reset)
    k_fill<<<(N_EDGES / 4 + 255) / 256, 256>>>(ei);
    k_gather<<<(N_NODES * 32 + 255) / 256, 256>>>((const float4*)x);
    cudaEventRecord(g_evG, 0);

    // reset cursors for the next call on s3 (overlaps the main GEMM)
    cudaStreamWaitEvent(g_s3, g_evG, 0);
    cudaMemsetAsync(d_cur, 0, N_NODES * NSH * sizeof(int), g_s3);
    cudaEventRecord(g_evCR, g_s3);

    // join, then final GEMM
    cudaStreamWaitEvent(0, g_evJoin, 0);
    cudaStreamWaitEvent(0, g_evBC, 0);
    k_main_gemm<<<dim3(HID / 64, (N_NODES + 127) / 128), 256>>>(bgcn, out);

    // rejoin the cursor-reset branch so the capture graph has no dangling work
    cudaStreamWaitEvent(0, g_evCR, 0);
}